// round 6
// baseline (speedup 1.0000x reference)
#include <cuda_runtime.h>
#include <math_constants.h>
#include <cstdint>

#define SEQS    32
#define HEADS   32
#define KVH     8
#define GQA     4
#define HS      128
#define BS      16
#define MAXB    128
#define CHUNK   128
#define NCHUNKS 16
#define TILE    16
#define QSCALE  0.088388347648318447f      // 1/sqrt(128)
#define LOG2E   1.4426950408889634f
#define RSTRIDE 34                         // float4 per row: 32 data + 2 pad (pad at END)

// Scratch partials (allocation-free rule). m is in log2 domain.
__device__ float g_part_m[SEQS][KVH][NCHUNKS][GQA];
__device__ float g_part_l[SEQS][KVH][NCHUNKS][GQA];
__device__ float g_part_acc[SEQS][KVH][NCHUNKS][GQA][HS];
__device__ unsigned g_count[SEQS][KVH];    // zero-init; last CTA resets to 0

__device__ __forceinline__ float ex2(float x) {
    float y; asm("ex2.approx.f32 %0, %1;" : "=f"(y) : "f"(x)); return y;  // ex2(-inf)=+0
}
__device__ __forceinline__ unsigned long long fma2(unsigned long long a, unsigned long long b,
                                                   unsigned long long c) {
    unsigned long long d;
    asm("fma.rn.f32x2 %0, %1, %2, %3;" : "=l"(d) : "l"(a), "l"(b), "l"(c));
    return d;
}
__device__ __forceinline__ unsigned long long mul2(unsigned long long a, unsigned long long b) {
    unsigned long long d;
    asm("mul.rn.f32x2 %0, %1, %2;" : "=l"(d) : "l"(a), "l"(b));
    return d;
}
__device__ __forceinline__ unsigned long long packf2(float lo, float hi) {
    unsigned long long d;
    asm("mov.b64 %0, {%1, %2};" : "=l"(d) : "f"(lo), "f"(hi));
    return d;
}
__device__ __forceinline__ float2 unpackf2(unsigned long long v) {
    float lo, hi;
    asm("mov.b64 {%0, %1}, %2;" : "=f"(lo), "=f"(hi) : "l"(v));
    return make_float2(lo, hi);
}
__device__ __forceinline__ void mbar_init(unsigned a, unsigned cnt) {
    asm volatile("mbarrier.init.shared.b64 [%0], %1;" :: "r"(a), "r"(cnt) : "memory");
}
__device__ __forceinline__ void mbar_expect(unsigned a, unsigned tx) {
    asm volatile("mbarrier.arrive.expect_tx.shared.b64 _, [%0], %1;" :: "r"(a), "r"(tx) : "memory");
}
__device__ __forceinline__ void mbar_wait(unsigned a, unsigned parity) {
    asm volatile(
        "{\n\t.reg .pred P;\n\t"
        "WAIT_%=:\n\t"
        "mbarrier.try_wait.parity.acquire.cta.shared::cta.b64 P, [%0], %1;\n\t"
        "@!P bra WAIT_%=;\n\t}"
        :: "r"(a), "r"(parity) : "memory");
}
__device__ __forceinline__ void bulkcp(unsigned dst, const void* src, unsigned bytes, unsigned mbar) {
    asm volatile(
        "cp.async.bulk.shared::cluster.global.mbarrier::complete_tx::bytes [%0], [%1], %2, [%3];"
        :: "r"(dst), "l"(src), "r"(bytes), "r"(mbar) : "memory");
}

__global__ __launch_bounds__(128) void attn_chunk_kernel(
    const float* __restrict__ query,
    const float* __restrict__ kcache,
    const float* __restrict__ vcache,
    const int*   __restrict__ btab,
    const int*   __restrict__ seq_lens,
    float*       __restrict__ out)
{
    const int c  = blockIdx.x;   // chunk
    const int kv = blockIdx.y;   // kv head
    const int s  = blockIdx.z;   // sequence

    const int len   = seq_lens[s];
    const int start = c * CHUNK;
    if (start >= len) return;
    const int nt     = min(CHUNK, len - start);
    const int ntiles = (nt + TILE - 1) / TILE;
    const int nch    = (len + CHUNK - 1) / CHUNK;

    __shared__ float4 sK[2][TILE * RSTRIDE];   // 2 x 8704 B
    __shared__ float4 sV[2][TILE * RSTRIDE];   // 2 x 8704 B
    __shared__ float4 sQ[GQA * RSTRIDE];
    __shared__ float  sP[TILE * GQA];
    __shared__ float  sWmax[4][GQA];
    __shared__ float  sLsum[4][GQA];
    __shared__ unsigned long long mbar[2];
    __shared__ int sIsLast;

    const int tid  = threadIdx.x;
    const int w    = tid >> 5;
    const int lane = tid & 31;

    // Score-phase roles: lane = h*16 + t*4 + g
    const int g_s = lane & 3;
    const int t_s = (lane >> 2) & 3;
    const int h   = lane >> 4;
    // PV-phase roles: lane = g*8 + dp
    const int g_p  = lane >> 3;
    const int dp   = lane & 7;
    const int jcol = w * 8 + dp;                 // float4 column 0..31

    // Load + pre-scale Q into smem (pad at row end, no mid-row adjust)
    {
        const int g = tid >> 5, j = tid & 31;
        const float4 qv = *reinterpret_cast<const float4*>(
            query + (size_t)s * (HEADS * HS) + (kv * GQA + g) * HS + j * 4);
        const float scl = QSCALE * LOG2E;
        sQ[g * RSTRIDE + j] = make_float4(qv.x * scl, qv.y * scl, qv.z * scl, qv.w * scl);
    }

    const int* bt  = btab + s * MAXB;
    const int blk0 = start >> 4;

    const unsigned skbase = (unsigned)__cvta_generic_to_shared(&sK[0][0]);
    const unsigned svbase = (unsigned)__cvta_generic_to_shared(&sV[0][0]);
    const unsigned mb0    = (unsigned)__cvta_generic_to_shared(&mbar[0]);
    const unsigned bufstride = (unsigned)(TILE * RSTRIDE * sizeof(float4));
    const unsigned rowstride = (unsigned)(RSTRIDE * sizeof(float4));   // 544

    if (tid == 0) { mbar_init(mb0, 1); mbar_init(mb0 + 8, 1); }
    __syncthreads();    // mbar + sQ visible

    // Warp 0 stages one 16-token page (K+V) with 32 x 512B bulk copies
    auto load_tile = [&](int buf, int ti) {
        if (w == 0) {
            const unsigned mb = mb0 + buf * 8;
            if (lane == 0) mbar_expect(mb, 2u * TILE * 512u);
            const int blk = __ldg(bt + blk0 + ti);
            const size_t pbase = (size_t)blk * (BS * KVH * HS) + (size_t)kv * HS;
            const int r = lane & 15;
            const float* src = ((lane < 16) ? kcache : vcache) + pbase + (size_t)r * (KVH * HS);
            const unsigned dst = ((lane < 16) ? skbase : svbase) + buf * bufstride + r * rowstride;
            bulkcp(dst, src, 512u, mb);
        }
    };

    load_tile(0, 0);
    if (ntiles > 1) load_tile(1, 1);

    float m_s = -CUDART_INF_F, m_p = -CUDART_INF_F, l_s = 0.f;
    unsigned long long acc0 = 0ull, acc1 = 0ull;     // packed (0.f,0.f)

    const int kb = (w * 4 + t_s) * RSTRIDE + h * 16;   // float4/u64x2 index
    const int qb = g_s * RSTRIDE + h * 16;

    for (int i = 0; i < ntiles; i++) {
        const int b = i & 1;
        mbar_wait(mb0 + b * 8, (i >> 1) & 1);            // tile i staged & visible

        // ---- QK: 64-dim partial dot per (token, head), packed f32x2 ----
        const ulonglong2* KfU = reinterpret_cast<const ulonglong2*>(sK[b]);
        const ulonglong2* QfU = reinterpret_cast<const ulonglong2*>(sQ);
        unsigned long long a0 = 0ull, a1 = 0ull;
#pragma unroll
        for (int dd = 0; dd < 16; dd++) {
            const ulonglong2 kk = KfU[kb + dd];
            const ulonglong2 qq = QfU[qb + dd];
            a0 = fma2(kk.x, qq.x, a0);
            a1 = fma2(kk.y, qq.y, a1);
        }
        const float2 f0 = unpackf2(a0), f1 = unpackf2(a1);
        float dot = (f0.x + f0.y) + (f1.x + f1.y);
        dot += __shfl_xor_sync(0xffffffffu, dot, 16);    // combine dim halves

        const int tok = start + i * TILE + (w * 4 + t_s);
        const float sc = (tok < len) ? dot : -CUDART_INF_F;

        float wm = sc;
        wm = fmaxf(wm, __shfl_xor_sync(0xffffffffu, wm, 8));
        wm = fmaxf(wm, __shfl_xor_sync(0xffffffffu, wm, 4));
        if (lane < 4) sWmax[w][lane] = wm;
        __syncthreads();

        const float tm_s = fmaxf(fmaxf(sWmax[0][g_s], sWmax[1][g_s]),
                                 fmaxf(sWmax[2][g_s], sWmax[3][g_s]));
        const float tm_p = fmaxf(fmaxf(sWmax[0][g_p], sWmax[1][g_p]),
                                 fmaxf(sWmax[2][g_p], sWmax[3][g_p]));

        const float mns = fmaxf(m_s, tm_s);
        const float p   = ex2(sc - mns);
        l_s = l_s * ex2(m_s - mns) + (h == 0 ? p : 0.f);
        m_s = mns;
        if (h == 0) sP[(w * 4 + t_s) * 4 + g_s] = p;

        const float mnp  = fmaxf(m_p, tm_p);
        const float corr = ex2(m_p - mnp);
        m_p = mnp;
        __syncthreads();                                  // sP visible

        // ---- PV: lane owns (head g_p, 4 dims), packed f32x2 ----
        const ulonglong2* VfU = reinterpret_cast<const ulonglong2*>(sV[b]);
        const unsigned long long corr2 = packf2(corr, corr);
        acc0 = mul2(acc0, corr2);
        acc1 = mul2(acc1, corr2);
#pragma unroll
        for (int t = 0; t < TILE; t++) {
            const ulonglong2 vv = VfU[t * RSTRIDE + jcol];
            const unsigned long long p2 = packf2(sP[t * 4 + g_p], sP[t * 4 + g_p]);
            acc0 = fma2(p2, vv.x, acc0);
            acc1 = fma2(p2, vv.y, acc1);
        }
        __syncthreads();                                  // buffer b + sP reusable

        if (i + 2 < ntiles) load_tile(b, i + 2);
    }

    // ---- epilogue: reduce l; write partials ----
    float L = l_s;
    L += __shfl_xor_sync(0xffffffffu, L, 16);
    L += __shfl_xor_sync(0xffffffffu, L, 8);
    L += __shfl_xor_sync(0xffffffffu, L, 4);
    if (lane < 4) sLsum[w][lane] = L;
    __syncthreads();
    if (w == 0 && lane < 4) {
        g_part_m[s][kv][c][lane] = m_s;
        g_part_l[s][kv][c][lane] =
            sLsum[0][lane] + sLsum[1][lane] + sLsum[2][lane] + sLsum[3][lane];
    }
    {
        const float2 a01 = unpackf2(acc0), a23 = unpackf2(acc1);
        *reinterpret_cast<float4*>(&g_part_acc[s][kv][c][g_p][jcol * 4]) =
            make_float4(a01.x, a01.y, a23.x, a23.y);
    }

    // ---- fused cross-chunk reduce: last CTA for (s,kv) combines & writes out ----
    __threadfence();
    __syncthreads();
    if (tid == 0) {
        const unsigned old = atomicAdd(&g_count[s][kv], 1u);
        sIsLast = (old == (unsigned)(nch - 1));
    }
    __syncthreads();
    if (sIsLast) {
        __threadfence();
        const int d = tid;   // 128 threads, one dim each
#pragma unroll
        for (int g = 0; g < GQA; g++) {
            float M = -CUDART_INF_F;
            for (int cc = 0; cc < nch; cc++) M = fmaxf(M, g_part_m[s][kv][cc][g]);
            float Lr = 0.f, A = 0.f;
            for (int cc = 0; cc < nch; cc++) {
                const float f = ex2(g_part_m[s][kv][cc][g] - M);
                Lr += f * g_part_l[s][kv][cc][g];
                A  += f * g_part_acc[s][kv][cc][g][d];
            }
            out[(size_t)s * (HEADS * HS) + (kv * GQA + g) * HS + d] = A / Lr;
        }
        if (tid == 0) g_count[s][kv] = 0;   // reset for next launch/replay
    }
}

extern "C" void kernel_launch(void* const* d_in, const int* in_sizes, int n_in,
                              void* d_out, int out_size)
{
    const float* query  = (const float*)d_in[0];
    const float* kcache = (const float*)d_in[1];
    const float* vcache = (const float*)d_in[2];
    const int*   btab   = (const int*)d_in[3];
    const int*   slens  = (const int*)d_in[4];
    float* out = (float*)d_out;

    dim3 grid1(NCHUNKS, KVH, SEQS);
    attn_chunk_kernel<<<grid1, 128>>>(query, kcache, vcache, btab, slens, out);
}